// round 16
// baseline (speedup 1.0000x reference)
#include <cuda_runtime.h>
#include <cuda_bf16.h>
#include <math.h>
#include <stdint.h>

#define NPTS   65536
#define CDIM   256
#define KCODES 2048

#define TH     512
#define MPT    256         // points per block
#define NT     64          // codes per chunk
#define NCH    32          // 2048 / 64
#define MARGIN 2.5e-4f
#define BIGF   3.4e38f

// ---- dynamic smem layout (bytes) ----
#define SA    0            // A tile: 256 rows x 512B (bf16, swizzled)
#define SB0   131072       // B chunk: 64 rows x 512B
#define SB1   163840
#define SBS   196608       // norms: 2048 f32
#define SAN   204800       // An: 256 f32
#define SMTOT 205824

// ---- device scratch ----
__device__ int      g_idx[NPTS];
__device__ float    g_cbn[KCODES];
__device__ uint32_t g_cbb[KCODES * 128];   // bf16x2-packed codebook
__device__ float    g_An[NPTS];
__device__ int      g_ccnt[NPTS];
__device__ int      g_cand[NPTS * 16];
__device__ int      g_cnt[KCODES];
__device__ double   g_loss;
__device__ int      g_qsmall[NPTS];
__device__ int      g_qfull[NPTS];
__device__ int      g_nsmall;
__device__ int      g_nfull;

// out layout (fp32): [z_q_st 16,777,216 | loss | perplexity | encodings]
#define OFF_LOSS 16777216
#define OFF_PERP 16777217
#define OFF_ENC  16777218

// ======================= helpers =======================
__device__ __forceinline__ uint32_t smem_u32(const void* p) {
    uint32_t a;
    asm("{ .reg .u64 t; cvta.to.shared.u64 t, %1; cvt.u32.u64 %0, t; }" : "=r"(a) : "l"(p));
    return a;
}
__device__ __forceinline__ uint32_t pack2(float a, float b) {
    __nv_bfloat162 t = __floats2bfloat162_rn(a, b);
    return *(uint32_t*)&t;
}
__device__ __forceinline__ void ldm4(uint32_t* r, uint32_t addr) {
    asm volatile("ldmatrix.sync.aligned.m8n8.x4.shared.b16 {%0,%1,%2,%3}, [%4];"
        : "=r"(r[0]), "=r"(r[1]), "=r"(r[2]), "=r"(r[3]) : "r"(addr));
}
__device__ __forceinline__ void mma16816(float* c, const uint32_t* a, const uint32_t* b) {
    asm volatile("mma.sync.aligned.m16n8k16.row.col.f32.bf16.bf16.f32 "
        "{%0,%1,%2,%3}, {%4,%5,%6,%7}, {%8,%9}, {%0,%1,%2,%3};"
        : "+f"(c[0]), "+f"(c[1]), "+f"(c[2]), "+f"(c[3])
        : "r"(a[0]), "r"(a[1]), "r"(a[2]), "r"(a[3]), "r"(b[0]), "r"(b[1]));
}
__device__ __forceinline__ void cp16(uint32_t dst, const void* src) {
    asm volatile("cp.async.cg.shared.global [%0], [%1], 16;" :: "r"(dst), "l"(src));
}
#define CP_COMMIT() asm volatile("cp.async.commit_group;" ::: "memory")
#define CP_WAIT0()  asm volatile("cp.async.wait_group 0;" ::: "memory")

// ======================= prep (fused): bf16 conversion + norms + zero =======================
__global__ void k_prep(const float* __restrict__ cb) {
    int i = blockIdx.x * blockDim.x + threadIdx.x;   // 262144 threads
    float2 v2 = ((const float2*)cb)[i];
    g_cbb[i] = pack2(v2.x, v2.y);

    if (i < KCODES) {
        const float4* row = (const float4*)(cb + (size_t)i * CDIM);
        float s = 0.f;
        #pragma unroll 4
        for (int c4 = 0; c4 < 64; ++c4) {
            float4 v = row[c4];
            s = __fadd_rn(s, __fmul_rn(v.x, v.x));
            s = __fadd_rn(s, __fmul_rn(v.y, v.y));
            s = __fadd_rn(s, __fmul_rn(v.z, v.z));
            s = __fadd_rn(s, __fmul_rn(v.w, v.w));
        }
        g_cbn[i] = s;
        g_cnt[i] = 0;
    }
    if (i == 0) { g_loss = 0.0; g_nsmall = 0; g_nfull = 0; }
}

// no-op spacers so k_argmin_mma is kernel launch #4 (ncu captures #4)
__global__ void k_nop() {}

// ======================= HMMA distance GEMM + streaming argmin =======================
__global__ __launch_bounds__(TH, 1)
void k_argmin_mma(const float* __restrict__ z, const float* __restrict__ cb) {
    extern __shared__ char smem[];
    const uint32_t sb = smem_u32(smem);
    const int tid  = threadIdx.x;
    const int lane = tid & 31;
    const int wid  = tid >> 5;         // 0..15
    const int wm   = wid >> 1;         // 0..7  (32 pts each)
    const int wn   = wid & 1;          // 0..1  (32 codes each)

    const int blk = blockIdx.x;        // 0..255
    const int b   = blk >> 2;
    const int hw0 = (blk & 3) << 8;    // 256 contiguous hw
    const int n0  = blk * MPT;
    const float* zb = z + (size_t)b * (CDIM * 1024) + hw0;

    float* bsn = (float*)(smem + SBS);
    float* sAn = (float*)(smem + SAN);

    // ---- stage B chunk 0 via cp.async (overlaps everything below) ----
    #pragma unroll
    for (int it = 0; it < 4; ++it) {
        int e = tid + it * TH;          // 0..2047
        int j = e >> 5, c8 = e & 31;
        cp16(sb + SB0 + j * 512 + ((c8 ^ (j & 7)) << 4),
             &g_cbb[(size_t)j * 128 + c8 * 4]);
    }
    CP_COMMIT();

    // ---- stage A (bf16 of z), swizzled [m][c]; 256 rows x 512B ----
    #pragma unroll 4
    for (int it = 0; it < 64; ++it) {
        int e = tid + it * TH;          // 0..32767
        int m = e & 255, c = (e >> 8) << 1;
        float v0 = zb[(size_t)c * 1024 + m];
        float v1 = zb[(size_t)(c + 1) * 1024 + m];
        uint32_t off = (uint32_t)(m * 512 + ((((c >> 3) ^ (m & 7))) << 4) + (c & 7) * 2);
        *(uint32_t*)(smem + SA + off) = pack2(v0, v1);
    }
    // ---- norms to smem ----
    for (int j = tid; j < KCODES; j += TH) bsn[j] = g_cbn[j];

    // ---- An exact (reference rounding) ----
    if (tid < MPT) {
        float p[32];
        #pragma unroll
        for (int l = 0; l < 32; ++l) p[l] = 0.f;
        #pragma unroll
        for (int i = 0; i < 8; ++i)
            #pragma unroll
            for (int l = 0; l < 32; ++l) {
                float t = zb[(size_t)(l + 32 * i) * 1024 + tid];
                p[l] = __fadd_rn(p[l], __fmul_rn(t, t));
            }
        #pragma unroll
        for (int off = 16; off >= 1; off >>= 1)
            #pragma unroll
            for (int l = 0; l < 16; ++l)
                if (l < off) p[l] = __fadd_rn(p[l], p[l + off]);
        sAn[tid] = p[0];
    }

    CP_WAIT0();
    __syncthreads();

    // per-slot argmin state: slot s = tm*2 + half  (4 m-rows per thread)
    float best[4], cv[4], ovfv[4];
    int   bk[4], ck[4];
    float An_r[4];
    #pragma unroll
    for (int s = 0; s < 4; ++s) {
        best[s] = BIGF; cv[s] = BIGF; ovfv[s] = BIGF;
        bk[s] = 0x7fffffff; ck[s] = 0x7fffffff;
        int tm = s >> 1, half = s & 1;
        An_r[s] = sAn[wm * 32 + tm * 16 + (lane >> 2) + half * 8];
    }

    const int pairc = (lane & 3) * 2;

    for (int i = 0; i < NCH; ++i) {
        const uint32_t sB = sb + ((i & 1) ? SB1 : SB0);

        // prefetch next chunk into the other buffer (cp.async)
        if (i + 1 < NCH) {
            const uint32_t dstb = ((i + 1) & 1) ? SB1 : SB0;
            const int kb2 = (i + 1) * NT;
            #pragma unroll
            for (int it = 0; it < 4; ++it) {
                int e = tid + it * TH;
                int j = e >> 5, c8 = e & 31;
                cp16(sb + dstb + j * 512 + ((c8 ^ (j & 7)) << 4),
                     &g_cbb[(size_t)(kb2 + j) * 128 + c8 * 4]);
            }
        }
        CP_COMMIT();

        float acc[2][4][4];
        #pragma unroll
        for (int tm = 0; tm < 2; ++tm)
            #pragma unroll
            for (int tn = 0; tn < 4; ++tn)
                #pragma unroll
                for (int r = 0; r < 4; ++r) acc[tm][tn][r] = 0.f;

        #pragma unroll
        for (int ks = 0; ks < 16; ++ks) {
            const int c0 = ks * 16;
            uint32_t a[2][4];
            #pragma unroll
            for (int tm = 0; tm < 2; ++tm) {
                int row = wm * 32 + tm * 16 + (lane & 15);
                int c   = c0 + ((lane >> 4) << 3);
                ldm4(a[tm], sb + SA + row * 512 + ((((c >> 3) ^ (row & 7))) << 4));
            }
            uint32_t bf[2][4];
            #pragma unroll
            for (int tp = 0; tp < 2; ++tp) {
                int j = wn * 32 + tp * 16 + ((lane >> 4) << 3) + (lane & 7);
                int c = c0 + ((lane >> 3) & 1) * 8;
                ldm4(bf[tp], sB + j * 512 + ((((c >> 3) ^ (j & 7))) << 4));
            }
            #pragma unroll
            for (int tm = 0; tm < 2; ++tm)
                #pragma unroll
                for (int tn = 0; tn < 4; ++tn)
                    mma16816(acc[tm][tn], a[tm], &bf[tn >> 1][(tn & 1) * 2]);
        }

        // ---- epilogue: cheap screen (v = Bk - 2m vs 2xMARGIN-slack threshold),
        //      exact detail path only when the screen fires ----
        const int kw = i * NT + wn * 32;
        float Bk[8];
        #pragma unroll
        for (int j = 0; j < 8; ++j)
            Bk[j] = bsn[kw + (j >> 1) * 8 + pairc + (j & 1)];

        #pragma unroll
        for (int s = 0; s < 4; ++s) {
            const int tm = s >> 1, half = s & 1;
            const float An = An_r[s];
            // conservative screen threshold: (best + 2*MARGIN) - An
            // (|exact_d - (An + v)| <= ~1e-4 < MARGIN, so no exact-window d escapes)
            const float t2 = __fsub_rn(__fadd_rn(best[s], 2.0f * MARGIN), An);
            float mn = BIGF;
            #pragma unroll
            for (int j = 0; j < 8; ++j) {
                float m = acc[tm][j >> 1][half * 2 + (j & 1)];
                mn = fminf(mn, fmaf(-2.0f, m, Bk[j]));
            }
            if (mn < t2) {
                // rare path: exact d's in ascending k, exact bookkeeping
                #pragma unroll
                for (int j = 0; j < 8; ++j) {
                    int k = kw + (j >> 1) * 8 + pairc + (j & 1);
                    float m = acc[tm][j >> 1][half * 2 + (j & 1)];
                    float d = __fadd_rn(__fadd_rn(An, -2.0f * m), Bk[j]);
                    if (d < best[s] + MARGIN) {
                        if (d < best[s]) {
                            float ob = best[s]; int obk = bk[s];
                            best[s] = d; bk[s] = k;
                            if (ob < d + MARGIN) {
                                if (cv[s] < d + MARGIN) {
                                    if (ob < cv[s]) { ovfv[s] = fminf(ovfv[s], cv[s]); cv[s] = ob; ck[s] = obk; }
                                    else            { ovfv[s] = fminf(ovfv[s], ob); }
                                } else { cv[s] = ob; ck[s] = obk; }
                            } else {
                                if (cv[s] >= d + MARGIN) { cv[s] = BIGF; ck[s] = 0x7fffffff; }
                            }
                        } else {
                            if (d < cv[s]) {
                                if (cv[s] < BIGF) ovfv[s] = fminf(ovfv[s], cv[s]);
                                cv[s] = d; ck[s] = k;
                            } else {
                                ovfv[s] = fminf(ovfv[s], d);
                            }
                        }
                    }
                }
            }
        }
        CP_WAIT0();
        __syncthreads();
    }

    // ---- dump per-thread state (reuse SA region: 5 x 8KB) ----
    float* Rbv = (float*)smem;
    int*   Rbk = (int*)(smem + 8192);
    float* Rcv = (float*)(smem + 16384);
    int*   Rck = (int*)(smem + 24576);
    float* Rof = (float*)(smem + 32768);
    const int cid = wn * 4 + (lane & 3);     // 0..7
    #pragma unroll
    for (int s = 0; s < 4; ++s) {
        int tm = s >> 1, half = s & 1;
        int m = wm * 32 + tm * 16 + (lane >> 2) + half * 8;
        int o = m * 8 + cid;
        Rbv[o] = best[s]; Rbk[o] = bk[s];
        Rcv[o] = cv[s];   Rck[o] = ck[s];
        Rof[o] = ovfv[s];
    }
    __syncthreads();

    // ---- merge per point; push ambiguous points to compacted queues ----
    if (tid < MPT) {
        const int m = tid;
        float gb = BIGF;
        #pragma unroll
        for (int c = 0; c < 8; ++c) {
            float v = Rbv[m * 8 + c];
            if (v < gb) gb = v;
        }
        bool full = false;
        int cnt = 0, cds[16];
        #pragma unroll
        for (int c = 0; c < 8; ++c) {
            int o = m * 8 + c;
            if (Rof[o] < gb + MARGIN) full = true;
            float v = Rbv[o];
            if (v < gb + MARGIN) { if (cnt < 16) cds[cnt] = Rbk[o]; ++cnt; }
            float w = Rcv[o];
            if (w < gb + MARGIN) { if (cnt < 16) cds[cnt] = Rck[o]; ++cnt; }
        }
        if (cnt > 16) full = true;
        int n = n0 + m;
        g_An[n] = sAn[m];
        if (full) {
            int p = atomicAdd(&g_nfull, 1);
            g_qfull[p] = n;
        } else if (cnt == 1) {
            g_idx[n] = cds[0];
        } else {
            g_ccnt[n] = cnt;
            for (int t = 0; t < cnt; ++t) g_cand[n * 16 + t] = cds[t];
            int p = atomicAdd(&g_nsmall, 1);
            g_qsmall[p] = n;
        }
    }
}

// ======================= recheck (fused): full scans + small candidates =======================
__global__ __launch_bounds__(256)
void k_recheck_both(const float* __restrict__ z, const float* __restrict__ cb) {
    const int tid = threadIdx.x;

    if (blockIdx.x < 256) {
        // ---- full path: block per queued point ----
        __shared__ float zs[CDIM];
        __shared__ float rv[256];
        __shared__ int   rk[256];
        const int nq = g_nfull;
        for (int q = blockIdx.x; q < nq; q += 256) {
            int n = g_qfull[q];
            const float* zrow = z + (size_t)(n >> 10) * (CDIM * 1024) + (n & 1023);
            if (tid < CDIM) zs[tid] = zrow[(size_t)tid * 1024];
            __syncthreads();

            const float A = g_An[n];
            float bd = BIGF;
            int   bkk = 0x7fffffff;
            #pragma unroll
            for (int j = 0; j < 8; ++j) {      // codes [8*tid, 8*tid+8) ascending
                int k = tid * 8 + j;
                const float4* c4 = (const float4*)(cb + (size_t)k * CDIM);
                float acc = 0.f;
                #pragma unroll 4
                for (int c0 = 0; c0 < 64; ++c0) {
                    float4 e = c4[c0];
                    acc = fmaf(zs[c0 * 4 + 0], e.x, acc);
                    acc = fmaf(zs[c0 * 4 + 1], e.y, acc);
                    acc = fmaf(zs[c0 * 4 + 2], e.z, acc);
                    acc = fmaf(zs[c0 * 4 + 3], e.w, acc);
                }
                float d = __fadd_rn(__fadd_rn(A, -2.0f * acc), g_cbn[k]);
                if (d < bd) { bd = d; bkk = k; }
            }
            rv[tid] = bd; rk[tid] = bkk;
            __syncthreads();
            for (int off = 128; off; off >>= 1) {
                if (tid < off) {
                    float ov = rv[tid + off]; int ok = rk[tid + off];
                    if (ov < rv[tid] || (ov == rv[tid] && ok < rk[tid])) { rv[tid] = ov; rk[tid] = ok; }
                }
                __syncthreads();
            }
            if (tid == 0) g_idx[n] = rk[0];
            __syncthreads();
        }
    } else {
        // ---- small path: warp per queued point ----
        const int lane = tid & 31;
        const int wgid = ((blockIdx.x - 256) * 256 + tid) >> 5;   // 0..4095
        const int nw   = (512 * 256) >> 5;
        const int nq   = g_nsmall;
        for (int q = wgid; q < nq; q += nw) {
            int n   = g_qsmall[q];
            int cnt = g_ccnt[n];
            const float* zrow = z + (size_t)(n >> 10) * (CDIM * 1024) + (n & 1023);
            const float A = g_An[n];

            float bd = BIGF;
            int   bkk = 0x7fffffff;
            if (lane < cnt) {
                int k = g_cand[n * 16 + lane];
                const float4* c4 = (const float4*)(cb + (size_t)k * CDIM);
                float acc = 0.f;
                #pragma unroll 4
                for (int c0 = 0; c0 < 64; ++c0) {
                    float4 e = c4[c0];
                    acc = fmaf(zrow[(size_t)(c0 * 4 + 0) * 1024], e.x, acc);
                    acc = fmaf(zrow[(size_t)(c0 * 4 + 1) * 1024], e.y, acc);
                    acc = fmaf(zrow[(size_t)(c0 * 4 + 2) * 1024], e.z, acc);
                    acc = fmaf(zrow[(size_t)(c0 * 4 + 3) * 1024], e.w, acc);
                }
                bd = __fadd_rn(__fadd_rn(A, -2.0f * acc), g_cbn[k]);
                bkk = k;
            }
            #pragma unroll
            for (int off = 16; off; off >>= 1) {
                float ov = __shfl_down_sync(0xffffffffu, bd, off);
                int   ok = __shfl_down_sync(0xffffffffu, bkk, off);
                if (ov < bd || (ov == bd && ok < bkk)) { bd = ov; bkk = ok; }
            }
            if (lane == 0) g_idx[n] = bkk;
        }
    }
}

// ======================= z_q_st + loss: 4 channels x 4 points per thread =======================
__global__ void k_zq(const float* __restrict__ z, const float* __restrict__ cb,
                     float* __restrict__ out) {
    int t = blockIdx.x * blockDim.x + threadIdx.x;   // 1,048,576 threads
    int hw = (t & 255) << 2;
    int c  = ((t >> 8) & 63) << 2;
    int b  = t >> 14;

    int4 idx4 = *(const int4*)&g_idx[(b << 10) | hw];
    const int idx[4] = {idx4.x, idx4.y, idx4.z, idx4.w};

    float4 er[4];
    #pragma unroll
    for (int i = 0; i < 4; ++i)
        er[i] = *(const float4*)(cb + (size_t)idx[i] * CDIM + c);
    float e_ij[4][4] = {
        {er[0].x, er[1].x, er[2].x, er[3].x},
        {er[0].y, er[1].y, er[2].y, er[3].y},
        {er[0].z, er[1].z, er[2].z, er[3].z},
        {er[0].w, er[1].w, er[2].w, er[3].w}};

    size_t base = ((size_t)(b * 256 + c)) * 1024 + hw;
    double v = 0.0;
    #pragma unroll
    for (int j = 0; j < 4; ++j) {
        float4 zv = *(const float4*)(z + base + (size_t)j * 1024);
        float zs[4] = {zv.x, zv.y, zv.z, zv.w};
        float ov[4];
        #pragma unroll
        for (int i = 0; i < 4; ++i) {
            float diff = __fsub_rn(e_ij[j][i], zs[i]);
            ov[i] = __fadd_rn(zs[i], diff);
            v += (double)__fmul_rn(diff, diff);
        }
        float4 w4 = {ov[0], ov[1], ov[2], ov[3]};
        *(float4*)(out + base + (size_t)j * 1024) = w4;
    }

    #pragma unroll
    for (int off = 16; off; off >>= 1)
        v += __shfl_down_sync(0xffffffffu, v, off);
    __shared__ double ws[8];
    int lane = threadIdx.x & 31, w = threadIdx.x >> 5;
    if (lane == 0) ws[w] = v;
    __syncthreads();
    if (w == 0) {
        double s = (lane < 8) ? ws[lane] : 0.0;
        #pragma unroll
        for (int off = 4; off; off >>= 1)
            s += __shfl_down_sync(0xffffffffu, s, off);
        if (lane == 0) atomicAdd(&g_loss, s);
    }
}

// ======================= encodings scatter + histogram (fused) =======================
__global__ void k_encset(float* __restrict__ out) {
    int n = blockIdx.x * blockDim.x + threadIdx.x;
    if (n < NPTS) {
        int idx = g_idx[n];
        atomicAdd(&g_cnt[idx], 1);
        out[OFF_ENC + (size_t)n * KCODES + idx] = 1.0f;
    }
}

// ======================= scalars =======================
__global__ void k_scalars(float* __restrict__ out) {
    __shared__ double ssum[256];
    int t = threadIdx.x;
    double s = 0.0;
    for (int k = t; k < KCODES; k += 256) {
        float em = (float)g_cnt[k] * (1.0f / 65536.0f);
        float lg = logf(__fadd_rn(em, 1e-10f));
        s += (double)__fmul_rn(em, lg);
    }
    ssum[t] = s;
    __syncthreads();
    for (int off = 128; off; off >>= 1) {
        if (t < off) ssum[t] += ssum[t + off];
        __syncthreads();
    }
    if (t == 0) {
        float S = (float)ssum[0];
        out[OFF_PERP] = expf(-S);
        double m = g_loss / 16777216.0;
        float mf = (float)m;
        out[OFF_LOSS] = __fadd_rn(mf, __fmul_rn(0.25f, mf));
    }
}

extern "C" void kernel_launch(void* const* d_in, const int* in_sizes, int n_in,
                              void* d_out, int out_size) {
    (void)out_size;
    const float* z  = (const float*)d_in[0];
    const float* cb = (const float*)d_in[1];
    if (n_in >= 2 && in_sizes[0] == KCODES * CDIM) {
        const float* t = z; z = cb; cb = t;
    }
    float* out = (float*)d_out;

    static cudaStream_t s2 = 0;
    static cudaEvent_t  ev_fork = 0, ev_idx = 0, ev_enc = 0;
    if (s2 == 0) {
        cudaStreamCreateWithFlags(&s2, cudaStreamNonBlocking);
        cudaEventCreateWithFlags(&ev_fork, cudaEventDisableTiming);
        cudaEventCreateWithFlags(&ev_idx, cudaEventDisableTiming);
        cudaEventCreateWithFlags(&ev_enc, cudaEventDisableTiming);
    }

    cudaFuncSetAttribute(k_argmin_mma, cudaFuncAttributeMaxDynamicSharedMemorySize, SMTOT);

    // fork: zero the encodings region on s2, overlapping the main pipeline
    cudaEventRecord(ev_fork, 0);
    cudaStreamWaitEvent(s2, ev_fork, 0);
    cudaMemsetAsync(out + OFF_ENC, 0, (size_t)NPTS * KCODES * sizeof(float), s2);

    k_prep        <<<262144 / 256, 256>>>(cb);                // kernel #1
    k_nop         <<<1, 32>>>();                              // kernel #2
    k_nop         <<<1, 32>>>();                              // kernel #3
    k_argmin_mma  <<<NPTS / MPT, TH, SMTOT>>>(z, cb);         // kernel #4 -> ncu capture
    k_recheck_both<<<768, 256>>>(z, cb);

    // after recheck, indices are final: run encset (s2) concurrently with k_zq (s0)
    cudaEventRecord(ev_idx, 0);
    cudaStreamWaitEvent(s2, ev_idx, 0);
    k_encset      <<<NPTS / 256, 256, 0, s2>>>(out);
    cudaEventRecord(ev_enc, s2);

    k_zq          <<<1048576 / 256, 256>>>(z, cb, out);

    cudaStreamWaitEvent(0, ev_enc, 0);
    k_scalars     <<<1, 256>>>(out);
}

// round 17
// speedup vs baseline: 1.0464x; 1.0464x over previous
#include <cuda_runtime.h>
#include <cuda_bf16.h>
#include <math.h>
#include <stdint.h>

#define NPTS   65536
#define CDIM   256
#define KCODES 2048

#define TH     512
#define MPT    256         // points per block
#define NT     64          // codes per chunk
#define NCH    32          // 2048 / 64
#define MARGIN 2.5e-4f
#define BIGF   3.4e38f

// ---- dynamic smem layout (bytes) ----
#define SA    0            // A tile: 256 rows x 512B (bf16, swizzled)
#define SB0   131072       // B chunk: 64 rows x 512B
#define SB1   163840
#define SBS   196608       // norms: 2048 f32
#define SAN   204800       // An: 256 f32
#define SMTOT 205824

// ---- device scratch ----
__device__ int      g_idx[NPTS];
__device__ float    g_cbn[KCODES];
__device__ uint32_t g_cbb[KCODES * 128];   // bf16x2-packed codebook
__device__ float    g_An[NPTS];
__device__ int      g_ccnt[NPTS];          // 1 = decided; >1 small queue; 100000 full
__device__ int      g_cand[NPTS * 16];
__device__ int      g_cnt[KCODES];
__device__ double   g_loss;
__device__ int      g_qsmall[NPTS];
__device__ int      g_qfull[NPTS];
__device__ int      g_nsmall;
__device__ int      g_nfull;

// out layout (fp32): [z_q_st 16,777,216 | loss | perplexity | encodings]
#define OFF_LOSS 16777216
#define OFF_PERP 16777217
#define OFF_ENC  16777218

// ======================= helpers =======================
__device__ __forceinline__ uint32_t smem_u32(const void* p) {
    uint32_t a;
    asm("{ .reg .u64 t; cvta.to.shared.u64 t, %1; cvt.u32.u64 %0, t; }" : "=r"(a) : "l"(p));
    return a;
}
__device__ __forceinline__ uint32_t pack2(float a, float b) {
    __nv_bfloat162 t = __floats2bfloat162_rn(a, b);
    return *(uint32_t*)&t;
}
__device__ __forceinline__ void ldm4(uint32_t* r, uint32_t addr) {
    asm volatile("ldmatrix.sync.aligned.m8n8.x4.shared.b16 {%0,%1,%2,%3}, [%4];"
        : "=r"(r[0]), "=r"(r[1]), "=r"(r[2]), "=r"(r[3]) : "r"(addr));
}
__device__ __forceinline__ void mma16816(float* c, const uint32_t* a, const uint32_t* b) {
    asm volatile("mma.sync.aligned.m16n8k16.row.col.f32.bf16.bf16.f32 "
        "{%0,%1,%2,%3}, {%4,%5,%6,%7}, {%8,%9}, {%0,%1,%2,%3};"
        : "+f"(c[0]), "+f"(c[1]), "+f"(c[2]), "+f"(c[3])
        : "r"(a[0]), "r"(a[1]), "r"(a[2]), "r"(a[3]), "r"(b[0]), "r"(b[1]));
}
__device__ __forceinline__ void cp16(uint32_t dst, const void* src) {
    asm volatile("cp.async.cg.shared.global [%0], [%1], 16;" :: "r"(dst), "l"(src));
}
#define CP_COMMIT() asm volatile("cp.async.commit_group;" ::: "memory")
#define CP_WAIT0()  asm volatile("cp.async.wait_group 0;" ::: "memory")

// ======================= prep (fused): bf16 conversion + norms + zero =======================
__global__ void k_prep(const float* __restrict__ cb) {
    int i = blockIdx.x * blockDim.x + threadIdx.x;   // 262144 threads
    float2 v2 = ((const float2*)cb)[i];
    g_cbb[i] = pack2(v2.x, v2.y);

    if (i < KCODES) {
        const float4* row = (const float4*)(cb + (size_t)i * CDIM);
        float s = 0.f;
        #pragma unroll 4
        for (int c4 = 0; c4 < 64; ++c4) {
            float4 v = row[c4];
            s = __fadd_rn(s, __fmul_rn(v.x, v.x));
            s = __fadd_rn(s, __fmul_rn(v.y, v.y));
            s = __fadd_rn(s, __fmul_rn(v.z, v.z));
            s = __fadd_rn(s, __fmul_rn(v.w, v.w));
        }
        g_cbn[i] = s;
        g_cnt[i] = 0;
    }
    if (i == 0) { g_loss = 0.0; g_nsmall = 0; g_nfull = 0; }
}

// ======================= HMMA distance GEMM + streaming argmin =======================
__global__ __launch_bounds__(TH, 1)
void k_argmin_mma(const float* __restrict__ z, const float* __restrict__ cb) {
    extern __shared__ char smem[];
    const uint32_t sb = smem_u32(smem);
    const int tid  = threadIdx.x;
    const int lane = tid & 31;
    const int wid  = tid >> 5;         // 0..15
    const int wm   = wid >> 1;         // 0..7  (32 pts each)
    const int wn   = wid & 1;          // 0..1  (32 codes each)

    const int blk = blockIdx.x;        // 0..255
    const int b   = blk >> 2;
    const int hw0 = (blk & 3) << 8;    // 256 contiguous hw
    const int n0  = blk * MPT;
    const float* zb = z + (size_t)b * (CDIM * 1024) + hw0;

    float* bsn = (float*)(smem + SBS);
    float* sAn = (float*)(smem + SAN);

    // ---- stage B chunk 0 via cp.async (overlaps everything below) ----
    #pragma unroll
    for (int it = 0; it < 4; ++it) {
        int e = tid + it * TH;          // 0..2047
        int j = e >> 5, c8 = e & 31;
        cp16(sb + SB0 + j * 512 + ((c8 ^ (j & 7)) << 4),
             &g_cbb[(size_t)j * 128 + c8 * 4]);
    }
    CP_COMMIT();

    // ---- stage A (bf16 of z), swizzled [m][c]; 256 rows x 512B ----
    #pragma unroll 4
    for (int it = 0; it < 64; ++it) {
        int e = tid + it * TH;          // 0..32767
        int m = e & 255, c = (e >> 8) << 1;
        float v0 = zb[(size_t)c * 1024 + m];
        float v1 = zb[(size_t)(c + 1) * 1024 + m];
        uint32_t off = (uint32_t)(m * 512 + ((((c >> 3) ^ (m & 7))) << 4) + (c & 7) * 2);
        *(uint32_t*)(smem + SA + off) = pack2(v0, v1);
    }
    // ---- norms to smem ----
    for (int j = tid; j < KCODES; j += TH) bsn[j] = g_cbn[j];

    // ---- An exact (reference rounding) ----
    if (tid < MPT) {
        float p[32];
        #pragma unroll
        for (int l = 0; l < 32; ++l) p[l] = 0.f;
        #pragma unroll
        for (int i = 0; i < 8; ++i)
            #pragma unroll
            for (int l = 0; l < 32; ++l) {
                float t = zb[(size_t)(l + 32 * i) * 1024 + tid];
                p[l] = __fadd_rn(p[l], __fmul_rn(t, t));
            }
        #pragma unroll
        for (int off = 16; off >= 1; off >>= 1)
            #pragma unroll
            for (int l = 0; l < 16; ++l)
                if (l < off) p[l] = __fadd_rn(p[l], p[l + off]);
        sAn[tid] = p[0];
    }

    CP_WAIT0();
    __syncthreads();

    // per-slot argmin state: slot s = tm*2 + half  (4 m-rows per thread)
    float best[4], cv[4], ovfv[4];
    int   bk[4], ck[4];
    float An_r[4];
    #pragma unroll
    for (int s = 0; s < 4; ++s) {
        best[s] = BIGF; cv[s] = BIGF; ovfv[s] = BIGF;
        bk[s] = 0x7fffffff; ck[s] = 0x7fffffff;
        int tm = s >> 1, half = s & 1;
        An_r[s] = sAn[wm * 32 + tm * 16 + (lane >> 2) + half * 8];
    }

    const int pairc = (lane & 3) * 2;

    for (int i = 0; i < NCH; ++i) {
        const uint32_t sB = sb + ((i & 1) ? SB1 : SB0);

        // prefetch next chunk into the other buffer (cp.async)
        if (i + 1 < NCH) {
            const uint32_t dstb = ((i + 1) & 1) ? SB1 : SB0;
            const int kb2 = (i + 1) * NT;
            #pragma unroll
            for (int it = 0; it < 4; ++it) {
                int e = tid + it * TH;
                int j = e >> 5, c8 = e & 31;
                cp16(sb + dstb + j * 512 + ((c8 ^ (j & 7)) << 4),
                     &g_cbb[(size_t)(kb2 + j) * 128 + c8 * 4]);
            }
        }
        CP_COMMIT();

        float acc[2][4][4];
        #pragma unroll
        for (int tm = 0; tm < 2; ++tm)
            #pragma unroll
            for (int tn = 0; tn < 4; ++tn)
                #pragma unroll
                for (int r = 0; r < 4; ++r) acc[tm][tn][r] = 0.f;

        #pragma unroll
        for (int ks = 0; ks < 16; ++ks) {
            const int c0 = ks * 16;
            uint32_t a[2][4];
            #pragma unroll
            for (int tm = 0; tm < 2; ++tm) {
                int row = wm * 32 + tm * 16 + (lane & 15);
                int c   = c0 + ((lane >> 4) << 3);
                ldm4(a[tm], sb + SA + row * 512 + ((((c >> 3) ^ (row & 7))) << 4));
            }
            uint32_t bf[2][4];
            #pragma unroll
            for (int tp = 0; tp < 2; ++tp) {
                int j = wn * 32 + tp * 16 + ((lane >> 4) << 3) + (lane & 7);
                int c = c0 + ((lane >> 3) & 1) * 8;
                ldm4(bf[tp], sB + j * 512 + ((((c >> 3) ^ (j & 7))) << 4));
            }
            #pragma unroll
            for (int tm = 0; tm < 2; ++tm)
                #pragma unroll
                for (int tn = 0; tn < 4; ++tn)
                    mma16816(acc[tm][tn], a[tm], &bf[tn >> 1][(tn & 1) * 2]);
        }

        // ---- epilogue: screen each slot's 8 d's, detail only if in-window ----
        const int kw = i * NT + wn * 32;
        float Bk[8];
        #pragma unroll
        for (int j = 0; j < 8; ++j)
            Bk[j] = bsn[kw + (j >> 1) * 8 + pairc + (j & 1)];

        #pragma unroll
        for (int s = 0; s < 4; ++s) {
            const int tm = s >> 1, half = s & 1;
            const float An = An_r[s];
            float mn = BIGF;
            #pragma unroll
            for (int j = 0; j < 8; ++j) {
                float m = acc[tm][j >> 1][half * 2 + (j & 1)];
                float d = __fadd_rn(__fadd_rn(An, -2.0f * m), Bk[j]);
                mn = fminf(mn, d);
            }
            if (mn < best[s] + MARGIN) {
                // rare path: recompute d's in ascending k, exact bookkeeping
                #pragma unroll
                for (int j = 0; j < 8; ++j) {
                    int k = kw + (j >> 1) * 8 + pairc + (j & 1);
                    float m = acc[tm][j >> 1][half * 2 + (j & 1)];
                    float d = __fadd_rn(__fadd_rn(An, -2.0f * m), Bk[j]);
                    if (d < best[s] + MARGIN) {
                        if (d < best[s]) {
                            float ob = best[s]; int obk = bk[s];
                            best[s] = d; bk[s] = k;
                            if (ob < d + MARGIN) {
                                if (cv[s] < d + MARGIN) {
                                    if (ob < cv[s]) { ovfv[s] = fminf(ovfv[s], cv[s]); cv[s] = ob; ck[s] = obk; }
                                    else            { ovfv[s] = fminf(ovfv[s], ob); }
                                } else { cv[s] = ob; ck[s] = obk; }
                            } else {
                                if (cv[s] >= d + MARGIN) { cv[s] = BIGF; ck[s] = 0x7fffffff; }
                            }
                        } else {
                            if (d < cv[s]) {
                                if (cv[s] < BIGF) ovfv[s] = fminf(ovfv[s], cv[s]);
                                cv[s] = d; ck[s] = k;
                            } else {
                                ovfv[s] = fminf(ovfv[s], d);
                            }
                        }
                    }
                }
            }
        }
        CP_WAIT0();
        __syncthreads();
    }

    // ---- dump per-thread state (reuse SA region: 5 x 8KB) ----
    float* Rbv = (float*)smem;
    int*   Rbk = (int*)(smem + 8192);
    float* Rcv = (float*)(smem + 16384);
    int*   Rck = (int*)(smem + 24576);
    float* Rof = (float*)(smem + 32768);
    const int cid = wn * 4 + (lane & 3);     // 0..7
    #pragma unroll
    for (int s = 0; s < 4; ++s) {
        int tm = s >> 1, half = s & 1;
        int m = wm * 32 + tm * 16 + (lane >> 2) + half * 8;
        int o = m * 8 + cid;
        Rbv[o] = best[s]; Rbk[o] = bk[s];
        Rcv[o] = cv[s];   Rck[o] = ck[s];
        Rof[o] = ovfv[s];
    }
    __syncthreads();

    // ---- merge per point; decided marker or compacted queues ----
    if (tid < MPT) {
        const int m = tid;
        float gb = BIGF;
        #pragma unroll
        for (int c = 0; c < 8; ++c) {
            float v = Rbv[m * 8 + c];
            if (v < gb) gb = v;
        }
        bool full = false;
        int cnt = 0, cds[16];
        #pragma unroll
        for (int c = 0; c < 8; ++c) {
            int o = m * 8 + c;
            if (Rof[o] < gb + MARGIN) full = true;
            float v = Rbv[o];
            if (v < gb + MARGIN) { if (cnt < 16) cds[cnt] = Rbk[o]; ++cnt; }
            float w = Rcv[o];
            if (w < gb + MARGIN) { if (cnt < 16) cds[cnt] = Rck[o]; ++cnt; }
        }
        if (cnt > 16) full = true;
        int n = n0 + m;
        g_An[n] = sAn[m];
        if (full) {
            g_ccnt[n] = 100000;
            int p = atomicAdd(&g_nfull, 1);
            g_qfull[p] = n;
        } else if (cnt == 1) {
            g_idx[n] = cds[0];
            g_ccnt[n] = 1;                  // decided marker
        } else {
            g_ccnt[n] = cnt;
            for (int t = 0; t < cnt; ++t) g_cand[n * 16 + t] = cds[t];
            int p = atomicAdd(&g_nsmall, 1);
            g_qsmall[p] = n;
        }
    }
}

// ======================= recheck (fused): full scans + small candidates =======================
__global__ __launch_bounds__(256)
void k_recheck_both(const float* __restrict__ z, const float* __restrict__ cb) {
    const int tid = threadIdx.x;

    if (blockIdx.x < 256) {
        // ---- full path: block per queued point ----
        __shared__ float zs[CDIM];
        __shared__ float rv[256];
        __shared__ int   rk[256];
        const int nq = g_nfull;
        for (int q = blockIdx.x; q < nq; q += 256) {
            int n = g_qfull[q];
            const float* zrow = z + (size_t)(n >> 10) * (CDIM * 1024) + (n & 1023);
            if (tid < CDIM) zs[tid] = zrow[(size_t)tid * 1024];
            __syncthreads();

            const float A = g_An[n];
            float bd = BIGF;
            int   bkk = 0x7fffffff;
            #pragma unroll
            for (int j = 0; j < 8; ++j) {      // codes [8*tid, 8*tid+8) ascending
                int k = tid * 8 + j;
                const float4* c4 = (const float4*)(cb + (size_t)k * CDIM);
                float acc = 0.f;
                #pragma unroll 4
                for (int c0 = 0; c0 < 64; ++c0) {
                    float4 e = c4[c0];
                    acc = fmaf(zs[c0 * 4 + 0], e.x, acc);
                    acc = fmaf(zs[c0 * 4 + 1], e.y, acc);
                    acc = fmaf(zs[c0 * 4 + 2], e.z, acc);
                    acc = fmaf(zs[c0 * 4 + 3], e.w, acc);
                }
                float d = __fadd_rn(__fadd_rn(A, -2.0f * acc), g_cbn[k]);
                if (d < bd) { bd = d; bkk = k; }
            }
            rv[tid] = bd; rk[tid] = bkk;
            __syncthreads();
            for (int off = 128; off; off >>= 1) {
                if (tid < off) {
                    float ov = rv[tid + off]; int ok = rk[tid + off];
                    if (ov < rv[tid] || (ov == rv[tid] && ok < rk[tid])) { rv[tid] = ov; rk[tid] = ok; }
                }
                __syncthreads();
            }
            if (tid == 0) g_idx[n] = rk[0];
            __syncthreads();
        }
    } else {
        // ---- small path: warp per queued point ----
        const int lane = tid & 31;
        const int wgid = ((blockIdx.x - 256) * 256 + tid) >> 5;   // 0..4095
        const int nw   = (512 * 256) >> 5;
        const int nq   = g_nsmall;
        for (int q = wgid; q < nq; q += nw) {
            int n   = g_qsmall[q];
            int cnt = g_ccnt[n];
            const float* zrow = z + (size_t)(n >> 10) * (CDIM * 1024) + (n & 1023);
            const float A = g_An[n];

            float bd = BIGF;
            int   bkk = 0x7fffffff;
            if (lane < cnt) {
                int k = g_cand[n * 16 + lane];
                const float4* c4 = (const float4*)(cb + (size_t)k * CDIM);
                float acc = 0.f;
                #pragma unroll 4
                for (int c0 = 0; c0 < 64; ++c0) {
                    float4 e = c4[c0];
                    acc = fmaf(zrow[(size_t)(c0 * 4 + 0) * 1024], e.x, acc);
                    acc = fmaf(zrow[(size_t)(c0 * 4 + 1) * 1024], e.y, acc);
                    acc = fmaf(zrow[(size_t)(c0 * 4 + 2) * 1024], e.z, acc);
                    acc = fmaf(zrow[(size_t)(c0 * 4 + 3) * 1024], e.w, acc);
                }
                bd = __fadd_rn(__fadd_rn(A, -2.0f * acc), g_cbn[k]);
                bkk = k;
            }
            #pragma unroll
            for (int off = 16; off; off >>= 1) {
                float ov = __shfl_down_sync(0xffffffffu, bd, off);
                int   ok = __shfl_down_sync(0xffffffffu, bkk, off);
                if (ov < bd || (ov == bd && ok < bkk)) { bd = ov; bkk = ok; }
            }
            if (lane == 0) g_idx[n] = bkk;
        }
    }
}

// ======================= z_q_st + loss, DECIDED points only (overlaps recheck) ==============
__global__ void k_zq_main(const float* __restrict__ z, const float* __restrict__ cb,
                          float* __restrict__ out) {
    int t = blockIdx.x * blockDim.x + threadIdx.x;   // 1,048,576 threads
    int hw = (t & 255) << 2;
    int c  = ((t >> 8) & 63) << 2;
    int b  = t >> 14;

    int4 idx4 = *(const int4*)&g_idx[(b << 10) | hw];
    int4 cc4  = *(const int4*)&g_ccnt[(b << 10) | hw];
    const int idx[4] = {idx4.x, idx4.y, idx4.z, idx4.w};
    const int dec[4] = {cc4.x == 1, cc4.y == 1, cc4.z == 1, cc4.w == 1};

    float e_ij[4][4];
    #pragma unroll
    for (int i = 0; i < 4; ++i) {
        if (dec[i]) {
            float4 e = *(const float4*)(cb + (size_t)idx[i] * CDIM + c);
            e_ij[0][i] = e.x; e_ij[1][i] = e.y; e_ij[2][i] = e.z; e_ij[3][i] = e.w;
        }
    }

    size_t base = ((size_t)(b * 256 + c)) * 1024 + hw;
    double v = 0.0;
    #pragma unroll
    for (int j = 0; j < 4; ++j) {
        float4 zv = *(const float4*)(z + base + (size_t)j * 1024);
        float zs[4] = {zv.x, zv.y, zv.z, zv.w};
        #pragma unroll
        for (int i = 0; i < 4; ++i) {
            if (dec[i]) {
                float diff = __fsub_rn(e_ij[j][i], zs[i]);
                out[base + (size_t)j * 1024 + i] = __fadd_rn(zs[i], diff);
                v += (double)__fmul_rn(diff, diff);
            }
        }
    }

    #pragma unroll
    for (int off = 16; off; off >>= 1)
        v += __shfl_down_sync(0xffffffffu, v, off);
    __shared__ double ws[8];
    int lane = threadIdx.x & 31, w = threadIdx.x >> 5;
    if (lane == 0) ws[w] = v;
    __syncthreads();
    if (w == 0) {
        double s = (lane < 8) ? ws[lane] : 0.0;
        #pragma unroll
        for (int off = 4; off; off >>= 1)
            s += __shfl_down_sync(0xffffffffu, s, off);
        if (lane == 0) atomicAdd(&g_loss, s);
    }
}

// ======================= z_q_st + loss fixup for QUEUED points (after recheck) ==============
__global__ void k_zq_fix(const float* __restrict__ z, const float* __restrict__ cb,
                         float* __restrict__ out) {
    const int ns = g_nsmall;
    const int total = (ns + g_nfull) * 64;           // 64 channel-groups per point
    const int stride = gridDim.x * blockDim.x;
    const int padded = (total + stride - 1) / stride * stride;
    int gid = blockIdx.x * blockDim.x + threadIdx.x;

    double v = 0.0;
    for (int i = gid; i < padded; i += stride) {
        if (i < total) {
            int qi = i >> 6, cg = i & 63;
            int n = (qi < ns) ? g_qsmall[qi] : g_qfull[qi - ns];
            int idx = g_idx[n];
            float4 e = *(const float4*)(cb + (size_t)idx * CDIM + cg * 4);
            float ev[4] = {e.x, e.y, e.z, e.w};
            int b = n >> 10, hw = n & 1023;
            size_t base = ((size_t)(b * 256 + cg * 4)) * 1024 + hw;
            #pragma unroll
            for (int j = 0; j < 4; ++j) {
                float zi = z[base + (size_t)j * 1024];
                float diff = __fsub_rn(ev[j], zi);
                out[base + (size_t)j * 1024] = __fadd_rn(zi, diff);
                v += (double)__fmul_rn(diff, diff);
            }
        }
    }
    #pragma unroll
    for (int off = 16; off; off >>= 1)
        v += __shfl_down_sync(0xffffffffu, v, off);
    if ((threadIdx.x & 31) == 0 && v != 0.0) atomicAdd(&g_loss, v);
}

// ======================= encodings scatter + histogram (fused) =======================
__global__ void k_encset(float* __restrict__ out) {
    int n = blockIdx.x * blockDim.x + threadIdx.x;
    if (n < NPTS) {
        int idx = g_idx[n];
        atomicAdd(&g_cnt[idx], 1);
        out[OFF_ENC + (size_t)n * KCODES + idx] = 1.0f;
    }
}

// ======================= scalars =======================
__global__ void k_scalars(float* __restrict__ out) {
    __shared__ double ssum[256];
    int t = threadIdx.x;
    double s = 0.0;
    for (int k = t; k < KCODES; k += 256) {
        float em = (float)g_cnt[k] * (1.0f / 65536.0f);
        float lg = logf(__fadd_rn(em, 1e-10f));
        s += (double)__fmul_rn(em, lg);
    }
    ssum[t] = s;
    __syncthreads();
    for (int off = 128; off; off >>= 1) {
        if (t < off) ssum[t] += ssum[t + off];
        __syncthreads();
    }
    if (t == 0) {
        float S = (float)ssum[0];
        out[OFF_PERP] = expf(-S);
        double m = g_loss / 16777216.0;
        float mf = (float)m;
        out[OFF_LOSS] = __fadd_rn(mf, __fmul_rn(0.25f, mf));
    }
}

extern "C" void kernel_launch(void* const* d_in, const int* in_sizes, int n_in,
                              void* d_out, int out_size) {
    (void)out_size;
    const float* z  = (const float*)d_in[0];
    const float* cb = (const float*)d_in[1];
    if (n_in >= 2 && in_sizes[0] == KCODES * CDIM) {
        const float* t = z; z = cb; cb = t;
    }
    float* out = (float*)d_out;

    static cudaStream_t s2 = 0;
    static cudaEvent_t  ev_fork = 0, ev_ms = 0, ev_arg = 0, ev_zqm = 0;
    if (s2 == 0) {
        cudaStreamCreateWithFlags(&s2, cudaStreamNonBlocking);
        cudaEventCreateWithFlags(&ev_fork, cudaEventDisableTiming);
        cudaEventCreateWithFlags(&ev_ms, cudaEventDisableTiming);
        cudaEventCreateWithFlags(&ev_arg, cudaEventDisableTiming);
        cudaEventCreateWithFlags(&ev_zqm, cudaEventDisableTiming);
    }

    cudaFuncSetAttribute(k_argmin_mma, cudaFuncAttributeMaxDynamicSharedMemorySize, SMTOT);

    // fork s2: zero the encodings region (overlaps prep+argmin)
    cudaEventRecord(ev_fork, 0);
    cudaStreamWaitEvent(s2, ev_fork, 0);
    cudaMemsetAsync(out + OFF_ENC, 0, (size_t)NPTS * KCODES * sizeof(float), s2);
    cudaEventRecord(ev_ms, s2);

    // main stream: prep -> argmin
    k_prep      <<<262144 / 256, 256>>>(cb);
    k_argmin_mma<<<NPTS / MPT, TH, SMTOT>>>(z, cb);
    cudaEventRecord(ev_arg, 0);

    // s2: z_q for decided points, concurrent with recheck on stream 0
    cudaStreamWaitEvent(s2, ev_arg, 0);
    k_zq_main   <<<1048576 / 256, 256, 0, s2>>>(z, cb, out);
    cudaEventRecord(ev_zqm, s2);

    // stream 0: recheck queued points, then fix their z_q rows + encodings
    k_recheck_both<<<768, 256>>>(z, cb);
    k_zq_fix    <<<512, 256>>>(z, cb, out);
    cudaStreamWaitEvent(0, ev_ms, 0);       // encodings memset done
    k_encset    <<<NPTS / 256, 256>>>(out);

    cudaStreamWaitEvent(0, ev_zqm, 0);      // decided-loss contribution done
    k_scalars   <<<1, 256>>>(out);
}